// round 11
// baseline (speedup 1.0000x reference)
#include <cuda_runtime.h>
#include <cstdint>
#include <math.h>

typedef unsigned long long ull;

#define NB 32
#define NS 512
#define NE 300
#define NHH 256
#define NT 12
#define NGATE 1024
#define TAG_START 10
#define TAG_STOP 11
#define FNEG (-10000.0f)

// ---------------- scratch (static device arrays; no allocation) ----------------
static __device__ float g_gates[2u * NS * NB * NGATE];   // [dir][m=s*32+b][1024]
static __device__ float g_h[2u * NS * NB * NHH];         // [dir][s][b][256]
static __device__ float g_feat[(size_t)NB * NS * NT];    // [b][s][12]

__device__ __forceinline__ float sigf(float x) { return 1.f / (1.f + __expf(-x)); }

__device__ __forceinline__ ull pack2(float lo, float hi) {
    ull r; asm("mov.b64 %0, {%1, %2};" : "=l"(r) : "f"(lo), "f"(hi)); return r;
}
__device__ __forceinline__ float2 unpack2(ull v) {
    float2 f; asm("mov.b64 {%0, %1}, %2;" : "=f"(f.x), "=f"(f.y) : "l"(v)); return f;
}
__device__ __forceinline__ void ffma2(ull& d, ull a, ull b) {
    asm("fma.rn.f32x2 %0, %1, %2, %0;" : "+l"(d) : "l"(a), "l"(b));
}
__device__ __forceinline__ uint32_t smem_u32(const void* p) {
    uint32_t a;
    asm("{ .reg .u64 t; cvta.to.shared.u64 t, %1; cvt.u32.u64 %0, t; }" : "=r"(a) : "l"(p));
    return a;
}

__global__ void nop_kernel() {}

// ---------------- Phase A: embedding gather + input GEMM (f32x2) ----------------
// BM=128, BN=64, BK=20. 256 threads, 8x4 microtile, k-paired accumulators. (R6 version)
__global__ void __launch_bounds__(256)
input_gemm_kernel(const int* __restrict__ inputs,
                  const float* __restrict__ embed,
                  const float* __restrict__ wih_f,
                  const float* __restrict__ bih_f,
                  const float* __restrict__ bhh_f,
                  const float* __restrict__ wih_b,
                  const float* __restrict__ bih_b,
                  const float* __restrict__ bhh_b) {
    const int dir = blockIdx.z;
    const float* __restrict__ wih = dir ? wih_b : wih_f;
    const float* __restrict__ bih = dir ? bih_b : bih_f;
    const float* __restrict__ bhh = dir ? bhh_b : bhh_f;
    const int n0 = blockIdx.x * 64;
    const int m0 = blockIdx.y * 128;

    __shared__ int    tok_s[128];
    __shared__ float2 A_s[10 * 128];
    __shared__ float2 W_s[10 * 64];

    const int tid = threadIdx.x;
    if (tid < 128) {
        const int m = m0 + tid;
        tok_s[tid] = inputs[(m & 31) * NS + (m >> 5)];
    }
    const int tn = tid & 15;
    const int tm = tid >> 4;

    ull acc[8][4];
#pragma unroll
    for (int i = 0; i < 8; i++)
#pragma unroll
        for (int j = 0; j < 4; j++) acc[i][j] = 0ull;

    __syncthreads();
    for (int kt = 0; kt < 15; kt++) {
        const int k0 = kt * 20;
        __syncthreads();
        for (int u = tid; u < 960; u += 256) {
            if (u < 640) {
                const int row = u / 5, c4 = u % 5;
                const float4 v = *(const float4*)(embed + (size_t)tok_s[row] * NE + k0 + c4 * 4);
                A_s[(c4 * 2) * 128 + row]     = make_float2(v.x, v.y);
                A_s[(c4 * 2 + 1) * 128 + row] = make_float2(v.z, v.w);
            } else {
                const int idx = u - 640;
                const int n = idx / 5, c4 = idx % 5;
                const float4 v = *(const float4*)(wih + (size_t)(n0 + n) * NE + k0 + c4 * 4);
                W_s[(c4 * 2) * 64 + n]     = make_float2(v.x, v.y);
                W_s[(c4 * 2 + 1) * 64 + n] = make_float2(v.z, v.w);
            }
        }
        __syncthreads();
#pragma unroll
        for (int kp = 0; kp < 10; kp++) {
            const ulonglong2* ap = (const ulonglong2*)(A_s + kp * 128 + tm * 8);
            const ulonglong2* wp = (const ulonglong2*)(W_s + kp * 64 + tn * 4);
            const ulonglong2 a0 = ap[0], a1 = ap[1], a2 = ap[2], a3 = ap[3];
            const ulonglong2 w0 = wp[0], w1 = wp[1];
            const ull a[8] = {a0.x, a0.y, a1.x, a1.y, a2.x, a2.y, a3.x, a3.y};
            const ull w[4] = {w0.x, w0.y, w1.x, w1.y};
#pragma unroll
            for (int i = 0; i < 8; i++)
#pragma unroll
                for (int j = 0; j < 4; j++) ffma2(acc[i][j], a[i], w[j]);
        }
    }

    const int ncol = n0 + tn * 4;
    const float4 b1 = *(const float4*)(bih + ncol);
    const float4 b2 = *(const float4*)(bhh + ncol);
    const float bx = b1.x + b2.x, by = b1.y + b2.y, bz = b1.z + b2.z, bw = b1.w + b2.w;
#pragma unroll
    for (int i = 0; i < 8; i++) {
        const int m = m0 + tm * 8 + i;
        const float2 s0 = unpack2(acc[i][0]);
        const float2 s1 = unpack2(acc[i][1]);
        const float2 s2 = unpack2(acc[i][2]);
        const float2 s3 = unpack2(acc[i][3]);
        const float4 o = make_float4(s0.x + s0.y + bx, s1.x + s1.y + by,
                                     s2.x + s2.y + bz, s3.x + s3.y + bw);
        *(float4*)(g_gates + ((size_t)dir * (NS * NB) + m) * NGATE + ncol) = o;
    }
}

// ---------------- Phase B: cluster-local bidirectional LSTM recurrence ----------------
// 128 CTAs = 16 clusters of 8. Cluster = (dir, batch-group of 4 batches), all 256 units.
// CTA rank r owns units [r*32, r*32+32): whh slice (128KB) in smem; h exchanged via DSMEM
// st.shared::cluster + split barrier.cluster. No global synchronization at all.
// smem: w2_s 128KB | h_s[2][4][260] 8320B | p_s [8][4][64] ull 16KB  => 155776 B
#define HPADF 260
#define HBUF_B 4160      // 4*260*4
__global__ void __launch_bounds__(256, 1) __cluster_dims__(8, 1, 1)
lstm_rec_kernel(const float* __restrict__ whh_f,
                const float* __restrict__ whh_b) {
    extern __shared__ char smraw[];
    ull*   w2_s = (ull*)smraw;                       // [k=256][rp=64]
    float* h0   = (float*)(smraw + 131072);          // [2][4][260]
    ull*   p_s  = (ull*)(smraw + 131072 + 2 * HBUF_B); // [ks=8][b=4][rp=64]

    const int tid = threadIdx.x;
    const int cid = blockIdx.x >> 3;
    const int rank = blockIdx.x & 7;       // cluster ctarank for (8,1,1)
    const int dir = cid >> 3;
    const int bgr = cid & 7;               // 8 batch-groups of 4
    const float* __restrict__ whh = dir ? whh_b : whh_f;

    // weights: w2_s[k*64 + rp] = pack(whh[row(2rp)][k], whh[row(2rp+1)][k])
    // local row r = u*4+g  ->  global whh row = g*256 + rank*32 + u
    for (int idx = tid; idx < 16384; idx += 256) {
        const int rp = idx >> 8, k = idx & 255;
        const int r0 = rp * 2;
        const int u = r0 >> 2, g0 = r0 & 3;
        const float w0 = whh[(size_t)(g0 * 256 + rank * 32 + u) * NHH + k];
        const float w1 = whh[(size_t)((g0 + 1) * 256 + rank * 32 + u) * NHH + k];
        w2_s[k * 64 + rp] = pack2(w0, w1);
    }

    const int lane = tid & 31;
    const int ks = tid >> 5;               // warp = k-slice (32 k)
    const int bL = lane >> 3, rq = lane & 7;   // compute roles: 4 batches x 8 rp-groups
    const int bE = tid >> 5, uE = tid & 31;    // epilogue roles (tid<128): warp=batch
    const int bglobal = bgr * 4 + bE;
    const int uglobal = rank * 32 + uE;
    float c_reg = 0.f;
    const size_t hb_dir = (size_t)dir * NS * NB * NHH;
    const float* const gdir = g_gates + (size_t)dir * (NS * NB * NGATE) + uglobal;
    const uint32_t hbase32 = smem_u32(smraw) + 131072;
    const uint32_t myoff = (uint32_t)(bE * (HPADF * 4) + uglobal * 4);

    // prefetch gates for t=0
    float n_i = 0.f, n_f = 0.f, n_g = 0.f, n_o = 0.f;
    if (tid < 128) {
        const int s0 = dir ? (NS - 1) : 0;
        const float* gp = gdir + ((size_t)s0 * NB + bglobal) * NGATE;
        n_i = __ldcg(gp); n_f = __ldcg(gp + 256); n_g = __ldcg(gp + 512); n_o = __ldcg(gp + 768);
    }
    __syncthreads();

    for (int t = 0; t < NS; t++) {
        const int s = dir ? (NS - 1 - t) : t;
        float a_i = n_i, a_f = n_f, a_g = n_g, a_o = n_o;
        if (tid < 128 && t + 1 < NS) {
            const int sn = dir ? (s - 1) : (s + 1);
            const float* gp = gdir + ((size_t)sn * NB + bglobal) * NGATE;
            n_i = __ldcg(gp); n_f = __ldcg(gp + 256); n_g = __ldcg(gp + 512); n_o = __ldcg(gp + 768);
        }

        if (t > 0) {
            asm volatile("barrier.cluster.wait.aligned;" ::: "memory");
            const int q = (t - 1) & 1;
            const float* hq = h0 + q * (HPADF * 4) + bL * HPADF;

            ull acc[8];
#pragma unroll
            for (int j = 0; j < 8; j++) acc[j] = 0ull;
            const int kbase = ks * 32;
#pragma unroll 4
            for (int kk = 0; kk < 32; kk++) {
                const int k = kbase + kk;
                const float h = hq[k];
                const ull hh = pack2(h, h);
                const ulonglong2* wrow = (const ulonglong2*)(w2_s + k * 64 + rq * 8);
#pragma unroll
                for (int j2 = 0; j2 < 4; j2++) {
                    const ulonglong2 w = wrow[j2];
                    ffma2(acc[j2 * 2],     hh, w.x);
                    ffma2(acc[j2 * 2 + 1], hh, w.y);
                }
            }
            ulonglong2* pp = (ulonglong2*)(p_s + (ks * 4 + bL) * 64 + rq * 8);
#pragma unroll
            for (int j2 = 0; j2 < 4; j2++)
                pp[j2] = make_ulonglong2(acc[j2 * 2], acc[j2 * 2 + 1]);
        }
        __syncthreads();

        if (tid < 128) {
            if (t > 0) {
#pragma unroll
                for (int kq = 0; kq < 8; kq++) {
                    const ulonglong2 v = *(const ulonglong2*)(p_s + (kq * 4 + bE) * 64 + 2 * uE);
                    const float2 vif = unpack2(v.x);
                    const float2 vgo = unpack2(v.y);
                    a_i += vif.x; a_f += vif.y;
                    a_g += vgo.x; a_o += vgo.y;
                }
            }
            const float ig = sigf(a_i), fg = sigf(a_f), og = sigf(a_o);
            const float tg = 2.f * sigf(2.f * a_g) - 1.f;             // tanh
            const float cn = fg * c_reg + ig * tg;
            const float hn = og * (2.f * sigf(2.f * cn) - 1.f);
            c_reg = cn;
            __stcg(g_h + hb_dir + ((size_t)s * NB + bglobal) * NHH + uglobal, hn);
            // deposit h to all 8 cluster CTAs' h_s[t&1]
            const uint32_t slot = hbase32 + (uint32_t)((t & 1) * HBUF_B) + myoff;
#pragma unroll
            for (int rr = 0; rr < 8; rr++) {
                uint32_t dst;
                asm("mapa.shared::cluster.u32 %0, %1, %2;" : "=r"(dst) : "r"(slot), "r"(rr));
                asm volatile("st.shared::cluster.f32 [%0], %1;" :: "r"(dst), "f"(hn) : "memory");
            }
        }
        asm volatile("barrier.cluster.arrive.aligned;" ::: "memory");
    }
    asm volatile("barrier.cluster.wait.aligned;" ::: "memory");
}

// ---------------- Phase C1: feats = hs @ fc_w^T + fc_b ----------------
__global__ void feats_kernel(const float* __restrict__ fc_w,
                             const float* __restrict__ fc_b) {
    __shared__ float fcw_s[NT * 512];
    __shared__ float fcb_s[NT];
    const int s = blockIdx.x;
    const int tid = threadIdx.x;
    for (int i = tid; i < NT * 512; i += 256) fcw_s[i] = fc_w[i];
    if (tid < NT) fcb_s[tid] = fc_b[tid];
    __syncthreads();

    const int w = tid >> 5, lane = tid & 31;
#pragma unroll
    for (int rep = 0; rep < 4; rep++) {
        const int b = w + rep * 8;
        const float4* hf = (const float4*)(g_h + ((size_t)s * NB + b) * NHH);
        const float4* hb = (const float4*)(g_h + (size_t)NS * NB * NHH + ((size_t)s * NB + b) * NHH);
        const float4 v0 = __ldcg(hf + lane);
        const float4 v1 = __ldcg(hf + lane + 32);
        const float4 v2 = __ldcg(hb + lane);
        const float4 v3 = __ldcg(hb + lane + 32);
#pragma unroll
        for (int tt = 0; tt < NT; tt++) {
            const float4* wr = (const float4*)(fcw_s + tt * 512);
            const float4 w0 = wr[lane];
            const float4 w1 = wr[lane + 32];
            const float4 w2 = wr[lane + 64];
            const float4 w3 = wr[lane + 96];
            float p = v0.x * w0.x + v0.y * w0.y + v0.z * w0.z + v0.w * w0.w
                    + v1.x * w1.x + v1.y * w1.y + v1.z * w1.z + v1.w * w1.w
                    + v2.x * w2.x + v2.y * w2.y + v2.z * w2.z + v2.w * w2.w
                    + v3.x * w3.x + v3.y * w3.y + v3.z * w3.z + v3.w * w3.w;
            p += __shfl_xor_sync(0xffffffffu, p, 16);
            p += __shfl_xor_sync(0xffffffffu, p, 8);
            p += __shfl_xor_sync(0xffffffffu, p, 4);
            p += __shfl_xor_sync(0xffffffffu, p, 2);
            p += __shfl_xor_sync(0xffffffffu, p, 1);
            if (lane == 0) g_feat[((size_t)b * NS + s) * NT + tt] = p + fcb_s[tt];
        }
    }
}

// ---------------- Phase C2: Viterbi, one warp per batch ----------------
__global__ void viterbi_kernel(const float* __restrict__ trans,
                               float* __restrict__ out, int out_size) {
    __shared__ float feat_s[NS * NT];
    __shared__ unsigned char bp_s[NS * NT];
    __shared__ float term_s[NT];
    const int b = blockIdx.x;
    const int lane = threadIdx.x;  // 32

    const float4* src = (const float4*)(g_feat + (size_t)b * NS * NT);
    float4* dst = (float4*)feat_s;
    for (int i = lane; i < (NS * NT) / 4; i += 32) dst[i] = __ldcg(src + i);

    const int tl = (lane < NT) ? lane : (NT - 1);
    float tr_reg[NT];
#pragma unroll
    for (int p = 0; p < NT; p++) tr_reg[p] = trans[p * NT + tl];
    const float tr_stop = trans[tl * NT + TAG_STOP];
    __syncwarp();

    float v = (lane == TAG_START) ? 0.f : FNEG;
    for (int s = 0; s < NS; s++) {
        float best = -3.0e38f;
        int bpi = 0;
#pragma unroll
        for (int p = 0; p < NT; p++) {
            const float sc = __shfl_sync(0xffffffffu, v, p) + tr_reg[p];
            if (sc > best) { best = sc; bpi = p; }
        }
        v = best + feat_s[s * NT + tl];
        if (lane < NT) bp_s[s * NT + lane] = (unsigned char)bpi;
    }
    if (lane < NT) term_s[lane] = v + tr_stop;
    __syncwarp();
    if (lane == 0) {
        float best = term_s[0];
        int last = 0;
#pragma unroll
        for (int tt = 1; tt < NT; tt++)
            if (term_s[tt] > best) { best = term_s[tt]; last = tt; }
        if (b < out_size) out[b] = best;
        const int base = NB + b * NS;
        if (base + NS - 1 < out_size) out[base + NS - 1] = (float)last;
        int tag = last;
        for (int s = NS - 1; s >= 0; s--) {
            const int pv = bp_s[s * NT + tag];
            if (s >= 1 && base + s - 1 < out_size) out[base + s - 1] = (float)pv;
            tag = pv;
        }
    }
}

// ---------------- launch ----------------
extern "C" void kernel_launch(void* const* d_in, const int* in_sizes, int n_in,
                              void* d_out, int out_size) {
    const int*   inputs = (const int*)d_in[0];
    const float* embed  = (const float*)d_in[1];
    const float* wih_f  = (const float*)d_in[2];
    const float* whh_f  = (const float*)d_in[3];
    const float* bih_f  = (const float*)d_in[4];
    const float* bhh_f  = (const float*)d_in[5];
    const float* wih_b  = (const float*)d_in[6];
    const float* whh_b  = (const float*)d_in[7];
    const float* bih_b  = (const float*)d_in[8];
    const float* bhh_b  = (const float*)d_in[9];
    const float* fc_w   = (const float*)d_in[10];
    const float* fc_b   = (const float*)d_in[11];
    const float* trans  = (const float*)d_in[12];

    const int lstm_smem = 131072 + 2 * HBUF_B + 16384;   // 155776 bytes
    cudaFuncSetAttribute(lstm_rec_kernel, cudaFuncAttributeMaxDynamicSharedMemorySize, lstm_smem);

    nop_kernel<<<1, 32>>>();   // keeps launch indices aligned with prior rounds (ncu slot)
    input_gemm_kernel<<<dim3(16, 128, 2), 256>>>(inputs, embed,
                                                 wih_f, bih_f, bhh_f,
                                                 wih_b, bih_b, bhh_b);
    nop_kernel<<<1, 32>>>();
    lstm_rec_kernel<<<128, 256, lstm_smem>>>(whh_f, whh_b);
    feats_kernel<<<NS, 256>>>(fc_w, fc_b);
    viterbi_kernel<<<NB, 32>>>(trans, (float*)d_out, out_size);
}